// round 5
// baseline (speedup 1.0000x reference)
#include <cuda_runtime.h>
#include <math.h>
#include <stdint.h>

// ---------------- problem constants ----------------
#define DEPTH 2
#define DIM   1024
#define HEADS 16
#define DH    64
#define BATCH 8
#define NQ    256
#define JTOT  1088
#define MS    1024
#define MROWS (BATCH*NQ)    // 2048
#define CROWS (BATCH*JTOT)  // 8704
#define FFH   4096
#define SCALE 0.125f
#define NJT   17            // JTOT / 64

// ---------------- scratch ----------------
__device__ float g_Q[MROWS * DIM];
__device__ float g_K[CROWS * DIM];
__device__ float g_V[CROWS * DIM];
__device__ float g_VT[(long)BATCH * DIM * JTOT];
__device__ float g_O[MROWS * DIM];
__device__ float g_Y[(long)MROWS * FFH];
__device__ float g_WqT[(long)DEPTH * DIM * DIM];
__device__ float g_WkT[(long)DEPTH * DIM * DIM];
__device__ float g_WvT[(long)DEPTH * DIM * DIM];
__device__ float g_WoT[(long)DEPTH * DIM * DIM];
__device__ float g_W1T[(long)DEPTH * 2 * FFH * DIM];
__device__ float g_W2T[(long)DEPTH * DIM * FFH];
__device__ float g_cosS[NQ * DH];
__device__ float g_sinS[NQ * DH];
__device__ float g_cosT[MS * DH];
__device__ float g_sinT[MS * DH];

// ---------------- ptx helpers ----------------
__device__ __forceinline__ float tf32r(float f) {
    uint32_t u;
    asm("cvt.rna.tf32.f32 %0, %1;" : "=r"(u) : "f"(f));
    return __uint_as_float(u);
}
__device__ __forceinline__ void ldsm4(uint32_t* r, uint32_t a) {
    asm volatile("ldmatrix.sync.aligned.m8n8.x4.shared.b16 {%0,%1,%2,%3}, [%4];"
                 : "=r"(r[0]), "=r"(r[1]), "=r"(r[2]), "=r"(r[3]) : "r"(a));
}
__device__ __forceinline__ void ldsm2(uint32_t* r, uint32_t a) {
    asm volatile("ldmatrix.sync.aligned.m8n8.x2.shared.b16 {%0,%1}, [%2];"
                 : "=r"(r[0]), "=r"(r[1]) : "r"(a));
}
__device__ __forceinline__ void mma_tf32(float* c, const uint32_t* a, const uint32_t* b) {
    asm volatile(
        "mma.sync.aligned.m16n8k8.row.col.f32.tf32.tf32.f32 "
        "{%0,%1,%2,%3}, {%4,%5,%6,%7}, {%8,%9}, {%0,%1,%2,%3};"
        : "+f"(c[0]), "+f"(c[1]), "+f"(c[2]), "+f"(c[3])
        : "r"(a[0]), "r"(a[1]), "r"(a[2]), "r"(a[3]), "r"(b[0]), "r"(b[1]));
}
__device__ __forceinline__ void mma_tf32b(float* c, const uint32_t* a, uint32_t b0, uint32_t b1) {
    asm volatile(
        "mma.sync.aligned.m16n8k8.row.col.f32.tf32.tf32.f32 "
        "{%0,%1,%2,%3}, {%4,%5,%6,%7}, {%8,%9}, {%0,%1,%2,%3};"
        : "+f"(c[0]), "+f"(c[1]), "+f"(c[2]), "+f"(c[3])
        : "r"(a[0]), "r"(a[1]), "r"(a[2]), "r"(a[3]), "r"(b0), "r"(b1));
}
__device__ __forceinline__ void cpa16(uint32_t d, const float* s) {
    asm volatile("cp.async.cg.shared.global [%0], [%1], 16;" :: "r"(d), "l"(s));
}

// ---------------- tf32 GEMM; EPI: 0=plain, 1=rope_q+scale, 2=rpe_bias+rope_k --
template <int BN, int EPI>
__global__ void __launch_bounds__(256)
gemm_tc(const float* __restrict__ A, const float* __restrict__ B,
        float* __restrict__ C, const float* __restrict__ Cadd,
        const float* __restrict__ bias,
        int K, int lda, int ldb, int ldc, float alpha,
        const float* __restrict__ ctab, const float* __restrict__ stab,
        const float* __restrict__ rpe_l, const int* __restrict__ rel_idx)
{
    constexpr int BM = 128;
    constexpr int ASZ = BM * 32, BSZ = BN * 32, STF = ASZ + BSZ;
    constexpr int WN = (BN == 128) ? 4 : 2;
    constexpr int WTM = BM / (8 / WN), WTN = BN / WN;
    constexpr int MI = WTM / 16, NI = WTN / 8;

    extern __shared__ float smdyn[];
    const uint32_t sb = (uint32_t)__cvta_generic_to_shared(smdyn);

    const int tid = threadIdx.x, warp = tid >> 5, lane = tid & 31;
    const int wm = warp / WN, wn = warp % WN;
    const int g = lane >> 2, t = lane & 3;
    const int bm0 = blockIdx.y * BM, bn0 = blockIdx.x * BN;

    const int arow = tid >> 3;
    const int cc   = tid & 7;

    const float* Ag = A + (long long)(bm0 + arow) * lda + cc * 4;
    const float* Bg = B + (long long)(bn0 + arow) * ldb + cc * 4;

    const int KT = K >> 5;

    auto load_stage = [&](int s, int kt) {
        if (kt < KT) {
            const int k0 = kt << 5;
            uint32_t ab = sb + (uint32_t)(s * STF) * 4u;
            #pragma unroll
            for (int i = 0; i < 4; i++) {
                int r = arow + i * 32;
                cpa16(ab + r * 128 + ((cc ^ (r & 7)) << 4),
                      Ag + (long long)i * 32 * lda + k0);
            }
            uint32_t bb = sb + (uint32_t)(s * STF + ASZ) * 4u;
            #pragma unroll
            for (int i = 0; i < BN / 32; i++) {
                int r = arow + i * 32;
                cpa16(bb + r * 128 + ((cc ^ (r & 7)) << 4),
                      Bg + (long long)i * 32 * ldb + k0);
            }
        }
        asm volatile("cp.async.commit_group;");
    };

    float acc[MI][NI][4];
    #pragma unroll
    for (int mi = 0; mi < MI; mi++)
        #pragma unroll
        for (int ni = 0; ni < NI; ni++)
            #pragma unroll
            for (int q = 0; q < 4; q++) acc[mi][ni][q] = 0.f;

    const int a_r  = lane & 15;
    const int a_kc = lane >> 4;
    const int b_r  = lane & 7;
    const int b_kc = (lane >> 3) & 1;

    load_stage(0, 0);
    load_stage(1, 1);

    for (int kt = 0; kt < KT; kt++) {
        asm volatile("cp.async.wait_group 1;");
        __syncthreads();
        load_stage((kt + 2) % 3, kt + 2);

        const int s = kt % 3;
        const uint32_t ab = sb + (uint32_t)(s * STF) * 4u;
        const uint32_t bb = ab + (uint32_t)ASZ * 4u;

        #pragma unroll
        for (int kk = 0; kk < 4; kk++) {
            uint32_t af[MI][4], bf[NI][2];
            #pragma unroll
            for (int mi = 0; mi < MI; mi++) {
                int r = wm * WTM + mi * 16 + a_r;
                int kc = kk * 2 + a_kc;
                ldsm4(af[mi], ab + r * 128 + ((kc ^ (r & 7)) << 4));
            }
            #pragma unroll
            for (int ni = 0; ni < NI; ni++) {
                int r = wn * WTN + ni * 8 + b_r;
                int kc = kk * 2 + b_kc;
                ldsm2(bf[ni], bb + r * 128 + ((kc ^ (r & 7)) << 4));
            }
            #pragma unroll
            for (int mi = 0; mi < MI; mi++)
                #pragma unroll
                for (int ni = 0; ni < NI; ni++)
                    mma_tf32(acc[mi][ni], af[mi], bf[ni]);
        }
    }

    #pragma unroll
    for (int mi = 0; mi < MI; mi++) {
        int row0 = bm0 + wm * WTM + mi * 16 + g;
        int jA = 0, jB = 0;
        if (EPI == 2) { jA = row0 % JTOT; jB = (row0 + 8) % JTOT; }
        #pragma unroll
        for (int ni = 0; ni < NI; ni++) {
            int col = bn0 + wn * WTN + ni * 8 + 2 * t;
            float v0 = alpha * acc[mi][ni][0];
            float v1 = alpha * acc[mi][ni][1];
            float v2 = alpha * acc[mi][ni][2];
            float v3 = alpha * acc[mi][ni][3];
            if (bias) { float b0 = bias[col], b1 = bias[col + 1]; v0 += b0; v1 += b1; v2 += b0; v3 += b1; }
            if (Cadd) {
                const float2 c0 = *(const float2*)(Cadd + (long long)row0 * ldc + col);
                const float2 c1 = *(const float2*)(Cadd + (long long)(row0 + 8) * ldc + col);
                v0 += c0.x; v1 += c0.y; v2 += c1.x; v3 += c1.y;
            }
            if (EPI == 1) {
                int d = col & (DH - 1);
                int nA = row0 & (NQ - 1), nB = (row0 + 8) & (NQ - 1);
                float cA0 = ctab[nA * DH + d],     sA0 = stab[nA * DH + d];
                float cA1 = ctab[nA * DH + d + 1], sA1 = stab[nA * DH + d + 1];
                float cB0 = ctab[nB * DH + d],     sB0 = stab[nB * DH + d];
                float cB1 = ctab[nB * DH + d + 1], sB1 = stab[nB * DH + d + 1];
                float o0 = (v0 * cA0 - v1 * sA0) * SCALE;
                float o1 = (v1 * cA1 + v0 * sA1) * SCALE;
                float o2 = (v2 * cB0 - v3 * sB0) * SCALE;
                float o3 = (v3 * cB1 + v2 * sB1) * SCALE;
                v0 = o0; v1 = o1; v2 = o2; v3 = o3;
            }
            if (EPI == 2) {
                int d = col & (DH - 1);
                int h = col >> 6;
                if (jA < MS) {
                    float bb2 = rpe_l[rel_idx[jA >> 8] * HEADS + h];
                    float k0 = v0 + bb2, k1 = v1 + bb2;
                    float c0 = ctab[jA * DH + d],     s0 = stab[jA * DH + d];
                    float c1 = ctab[jA * DH + d + 1], s1 = stab[jA * DH + d + 1];
                    v0 = k0 * c0 - k1 * s0;
                    v1 = k1 * c1 + k0 * s1;
                }
                if (jB < MS) {
                    float bb2 = rpe_l[rel_idx[jB >> 8] * HEADS + h];
                    float k0 = v2 + bb2, k1 = v3 + bb2;
                    float c0 = ctab[jB * DH + d],     s0 = stab[jB * DH + d];
                    float c1 = ctab[jB * DH + d + 1], s1 = stab[jB * DH + d + 1];
                    v2 = k0 * c0 - k1 * s0;
                    v3 = k1 * c1 + k0 * s1;
                }
            }
            *(float2*)(C + (long long)row0 * ldc + col) = make_float2(v0, v1);
            *(float2*)(C + (long long)(row0 + 8) * ldc + col) = make_float2(v2, v3);
        }
    }
}

// ---------------- FFN1 + GEGLU fused ----------------
__global__ void __launch_bounds__(256)
gemm_ffn1(const float* __restrict__ A, const float* __restrict__ B,
          float* __restrict__ Y, const float* __restrict__ b1l)
{
    constexpr int BM = 128, BN = 64;
    constexpr int ASZ = BM * 32, BSZ = BN * 32, STF = ASZ + 2 * BSZ;
    constexpr int WTM = 32, WTN = 32, MI = 2, NI = 4;
    const int KT = 32;

    extern __shared__ float smdyn[];
    const uint32_t sb = (uint32_t)__cvta_generic_to_shared(smdyn);

    const int tid = threadIdx.x, warp = tid >> 5, lane = tid & 31;
    const int wm = warp >> 1, wn = warp & 1;
    const int g = lane >> 2, t = lane & 3;
    const int bm0 = blockIdx.y * BM, bn0 = blockIdx.x * BN;

    const int arow = tid >> 3;
    const int cc   = tid & 7;

    const float* Ag  = A + (long long)(bm0 + arow) * DIM + cc * 4;
    const float* Bga = B + (long long)(bn0 + arow) * DIM + cc * 4;
    const float* Bgg = B + (long long)(FFH + bn0 + arow) * DIM + cc * 4;

    auto load_stage = [&](int s, int kt) {
        if (kt < KT) {
            const int k0 = kt << 5;
            uint32_t ab = sb + (uint32_t)(s * STF) * 4u;
            #pragma unroll
            for (int i = 0; i < 4; i++) {
                int r = arow + i * 32;
                cpa16(ab + r * 128 + ((cc ^ (r & 7)) << 4),
                      Ag + (long long)i * 32 * DIM + k0);
            }
            uint32_t bba = sb + (uint32_t)(s * STF + ASZ) * 4u;
            uint32_t bbg = bba + (uint32_t)BSZ * 4u;
            #pragma unroll
            for (int i = 0; i < 2; i++) {
                int r = arow + i * 32;
                cpa16(bba + r * 128 + ((cc ^ (r & 7)) << 4),
                      Bga + (long long)i * 32 * DIM + k0);
                cpa16(bbg + r * 128 + ((cc ^ (r & 7)) << 4),
                      Bgg + (long long)i * 32 * DIM + k0);
            }
        }
        asm volatile("cp.async.commit_group;");
    };

    float acca[MI][NI][4], accg[MI][NI][4];
    #pragma unroll
    for (int mi = 0; mi < MI; mi++)
        #pragma unroll
        for (int ni = 0; ni < NI; ni++)
            #pragma unroll
            for (int q = 0; q < 4; q++) { acca[mi][ni][q] = 0.f; accg[mi][ni][q] = 0.f; }

    const int a_r  = lane & 15;
    const int a_kc = lane >> 4;
    const int b_r  = lane & 7;
    const int b_kc = (lane >> 3) & 1;

    load_stage(0, 0);
    load_stage(1, 1);

    for (int kt = 0; kt < KT; kt++) {
        asm volatile("cp.async.wait_group 1;");
        __syncthreads();
        load_stage((kt + 2) % 3, kt + 2);

        const int s = kt % 3;
        const uint32_t ab  = sb + (uint32_t)(s * STF) * 4u;
        const uint32_t bba = ab + (uint32_t)ASZ * 4u;
        const uint32_t bbg = bba + (uint32_t)BSZ * 4u;

        #pragma unroll
        for (int kk = 0; kk < 4; kk++) {
            uint32_t af[MI][4], bfa[NI][2], bfg[NI][2];
            #pragma unroll
            for (int mi = 0; mi < MI; mi++) {
                int r = wm * WTM + mi * 16 + a_r;
                int kc = kk * 2 + a_kc;
                ldsm4(af[mi], ab + r * 128 + ((kc ^ (r & 7)) << 4));
            }
            #pragma unroll
            for (int ni = 0; ni < NI; ni++) {
                int r = wn * WTN + ni * 8 + b_r;
                int kc = kk * 2 + b_kc;
                ldsm2(bfa[ni], bba + r * 128 + ((kc ^ (r & 7)) << 4));
                ldsm2(bfg[ni], bbg + r * 128 + ((kc ^ (r & 7)) << 4));
            }
            #pragma unroll
            for (int mi = 0; mi < MI; mi++)
                #pragma unroll
                for (int ni = 0; ni < NI; ni++) {
                    mma_tf32(acca[mi][ni], af[mi], bfa[ni]);
                    mma_tf32(accg[mi][ni], af[mi], bfg[ni]);
                }
        }
    }

    #pragma unroll
    for (int mi = 0; mi < MI; mi++) {
        int row0 = bm0 + wm * WTM + mi * 16 + g;
        #pragma unroll
        for (int ni = 0; ni < NI; ni++) {
            int col = bn0 + wn * WTN + ni * 8 + 2 * t;
            float ba0 = b1l[col], ba1 = b1l[col + 1];
            float bg0 = b1l[FFH + col], bg1 = b1l[FFH + col + 1];
            #pragma unroll
            for (int half = 0; half < 2; half++) {
                float a0 = acca[mi][ni][half * 2 + 0] + ba0;
                float a1 = acca[mi][ni][half * 2 + 1] + ba1;
                float g0 = accg[mi][ni][half * 2 + 0] + bg0;
                float g1 = accg[mi][ni][half * 2 + 1] + bg1;
                float y0 = a0 * (0.5f * g0 * (1.0f + erff(g0 * 0.70710678118654752f)));
                float y1 = a1 * (0.5f * g1 * (1.0f + erff(g1 * 0.70710678118654752f)));
                *(float2*)(Y + (long long)(row0 + half * 8) * FFH + col) = make_float2(y0, y1);
            }
        }
    }
}

// ---------------- flash attention (fixed cp.async group discipline) ----------
__global__ void __launch_bounds__(256)
flash_attn(const float* __restrict__ Q, const float* __restrict__ K,
           const float* __restrict__ VT, float* __restrict__ O)
{
    extern __shared__ float sm[];
    const uint32_t sb = (uint32_t)__cvta_generic_to_shared(sm);
    const uint32_t qb = sb;
    const uint32_t kb = sb + 8192u * 4u;
    const uint32_t vb = sb + 16384u * 4u;
    const uint32_t pb = sb + 24576u * 4u;

    const int tid = threadIdx.x, warp = tid >> 5, lane = tid & 31;
    const int g = lane >> 2, t = lane & 3;
    const int m0 = blockIdx.x * 128;
    const int z = blockIdx.y;
    const int b = z >> 4, h = z & 15;

    const float* Qg = Q + ((long long)(b * NQ + m0)) * DIM + h * DH;
    const float* Kg = K + (long long)b * JTOT * DIM + h * DH;
    const float* Vg = VT + (long long)b * DIM * JTOT + (long long)h * DH * JTOT;
    float* Og = O + ((long long)(b * NQ + m0)) * DIM + h * DH;

    auto load_kv_body = [&](int s, int jt) {
        #pragma unroll
        for (int i = 0; i < 4; i++) {
            int idx = tid + i * 256;
            int cc = idx & 7, r = (idx >> 3) & 63, hf = idx >> 9;
            uint32_t off = (uint32_t)(s * 4096 + (hf * 64 + r) * 32) * 4u + ((cc ^ (r & 7)) << 4);
            cpa16(kb + off, Kg + (long long)(jt * 64 + r) * DIM + hf * 32 + cc * 4);
            cpa16(vb + off, Vg + (long long)r * JTOT + jt * 64 + hf * 32 + cc * 4);
        }
    };

    // group 1: Q + kv0
    #pragma unroll
    for (int i = 0; i < 8; i++) {
        int idx = tid + i * 256;
        int cc = idx & 7, r = (idx >> 3) & 127, hf = idx >> 10;
        cpa16(qb + (uint32_t)(hf * 128 + r) * 128u + ((cc ^ (r & 7)) << 4),
              Qg + (long long)r * DIM + hf * 32 + cc * 4);
    }
    load_kv_body(0, 0);
    asm volatile("cp.async.commit_group;");
    // group 2: kv1
    load_kv_body(1, 1);
    asm volatile("cp.async.commit_group;");

    float acco[8][4];
    #pragma unroll
    for (int ni = 0; ni < 8; ni++)
        #pragma unroll
        for (int q = 0; q < 4; q++) acco[ni][q] = 0.f;
    float mr0 = -INFINITY, mr1 = -INFINITY, l0 = 0.f, l1 = 0.f;

    const int fr = lane & 15;
    const int fc = lane >> 4;

    for (int jt = 0; jt < NJT; jt++) {
        const int s = jt & 1;
        asm volatile("cp.async.wait_group 1;");
        __syncthreads();

        // ---- S = Q @ K^T ----
        float accs[8][4];
        #pragma unroll
        for (int ni = 0; ni < 8; ni++)
            #pragma unroll
            for (int q = 0; q < 4; q++) accs[ni][q] = 0.f;

        #pragma unroll
        for (int kk = 0; kk < 8; kk++) {
            const int hf = kk >> 2;
            const int kc = (kk & 3) * 2 + fc;
            uint32_t a[4];
            {
                int r = warp * 16 + fr;
                ldsm4(a, qb + (uint32_t)(hf * 128 + r) * 128u + ((kc ^ (r & 7)) << 4));
            }
            #pragma unroll
            for (int p = 0; p < 4; p++) {
                int r = p * 16 + fr;
                uint32_t bf[4];
                ldsm4(bf, kb + (uint32_t)(s * 4096 + (hf * 64 + r) * 32) * 4u + ((kc ^ (r & 7)) << 4));
                mma_tf32b(accs[2 * p],     a, bf[0], bf[2]);
                mma_tf32b(accs[2 * p + 1], a, bf[1], bf[3]);
            }
        }

        // ---- online softmax ----
        float vm0 = -INFINITY, vm1 = -INFINITY;
        #pragma unroll
        for (int ni = 0; ni < 8; ni++) {
            vm0 = fmaxf(vm0, fmaxf(accs[ni][0], accs[ni][1]));
            vm1 = fmaxf(vm1, fmaxf(accs[ni][2], accs[ni][3]));
        }
        vm0 = fmaxf(vm0, __shfl_xor_sync(0xffffffffu, vm0, 1));
        vm0 = fmaxf(vm0, __shfl_xor_sync(0xffffffffu, vm0, 2));
        vm1 = fmaxf(vm1, __shfl_xor_sync(0xffffffffu, vm1, 1));
        vm1 = fmaxf(vm1, __shfl_xor_sync(0xffffffffu, vm1, 2));
        float mn0 = fmaxf(mr0, vm0), mn1 = fmaxf(mr1, vm1);
        float sc0 = __expf(mr0 - mn0), sc1 = __expf(mr1 - mn1);

        float ps0 = 0.f, ps1 = 0.f;
        float pv[8][4];
        #pragma unroll
        for (int ni = 0; ni < 8; ni++) {
            pv[ni][0] = tf32r(__expf(accs[ni][0] - mn0));
            pv[ni][1] = tf32r(__expf(accs[ni][1] - mn0));
            pv[ni][2] = tf32r(__expf(accs[ni][2] - mn1));
            pv[ni][3] = tf32r(__expf(accs[ni][3] - mn1));
            ps0 += pv[ni][0] + pv[ni][1];
            ps1 += pv[ni][2] + pv[ni][3];
        }
        ps0 += __shfl_xor_sync(0xffffffffu, ps0, 1);
        ps0 += __shfl_xor_sync(0xffffffffu, ps0, 2);
        ps1 += __shfl_xor_sync(0xffffffffu, ps1, 1);
        ps1 += __shfl_xor_sync(0xffffffffu, ps1, 2);
        l0 = l0 * sc0 + ps0;
        l1 = l1 * sc1 + ps1;
        mr0 = mn0; mr1 = mn1;
        #pragma unroll
        for (int ni = 0; ni < 8; ni++) {
            acco[ni][0] *= sc0; acco[ni][1] *= sc0;
            acco[ni][2] *= sc1; acco[ni][3] *= sc1;
        }

        // ---- store P (own rows only -> warp-local ordering suffices) ----
        const int r0 = warp * 16 + g, r1 = r0 + 8;
        #pragma unroll
        for (int ni = 0; ni < 8; ni++) {
            int hf = ni >> 2;
            int cc = (ni & 3) * 2 + (t >> 1);
            uint32_t ofs = (uint32_t)((t & 1) * 8);
            uint32_t a0 = pb + (uint32_t)(hf * 128 + r0) * 128u + ((cc ^ (r0 & 7)) << 4) + ofs;
            uint32_t a1 = pb + (uint32_t)(hf * 128 + r1) * 128u + ((cc ^ (r1 & 7)) << 4) + ofs;
            asm volatile("st.shared.v2.f32 [%0], {%1,%2};" :: "r"(a0), "f"(pv[ni][0]), "f"(pv[ni][1]));
            asm volatile("st.shared.v2.f32 [%0], {%1,%2};" :: "r"(a1), "f"(pv[ni][2]), "f"(pv[ni][3]));
        }
        __syncwarp();

        // ---- O += P @ V ----
        #pragma unroll
        for (int kk = 0; kk < 8; kk++) {
            const int hf = kk >> 2;
            const int kc = (kk & 3) * 2 + fc;
            uint32_t a[4];
            {
                int r = warp * 16 + fr;
                ldsm4(a, pb + (uint32_t)(hf * 128 + r) * 128u + ((kc ^ (r & 7)) << 4));
            }
            #pragma unroll
            for (int p = 0; p < 4; p++) {
                int r = p * 16 + fr;
                uint32_t bf[4];
                ldsm4(bf, vb + (uint32_t)(s * 4096 + (hf * 64 + r) * 32) * 4u + ((kc ^ (r & 7)) << 4));
                mma_tf32b(acco[2 * p],     a, bf[0], bf[2]);
                mma_tf32b(acco[2 * p + 1], a, bf[1], bf[3]);
            }
        }
        __syncthreads();

        if (jt + 2 < NJT) load_kv_body(s, jt + 2);
        asm volatile("cp.async.commit_group;");
    }

    float inv0 = 1.f / l0, inv1 = 1.f / l1;
    const int r0 = warp * 16 + g, r1 = r0 + 8;
    #pragma unroll
    for (int ni = 0; ni < 8; ni++) {
        int col = ni * 8 + 2 * t;
        *(float2*)(Og + (long long)r0 * DIM + col) =
            make_float2(acco[ni][0] * inv0, acco[ni][1] * inv0);
        *(float2*)(Og + (long long)r1 * DIM + col) =
            make_float2(acco[ni][2] * inv1, acco[ni][3] * inv1);
    }
}

// ---------------- batched weight transpose (single launch) ----------------
__global__ void __launch_bounds__(256)
wtrans_all(const float* __restrict__ Wq, const float* __restrict__ Wk,
           const float* __restrict__ Wv, const float* __restrict__ Wo,
           const float* __restrict__ W1, const float* __restrict__ W2,
           float* __restrict__ WqT, float* __restrict__ WkT,
           float* __restrict__ WvT, float* __restrict__ WoT,
           float* __restrict__ W1T, float* __restrict__ W2T)
{
    __shared__ float tbuf[32][33];
    const float* ins[6] = {Wq, Wk, Wv, Wo, W1, W2};
    float* outs[6] = {WqT, WkT, WvT, WoT, W1T, W2T};
    const int Rs[6] = {DIM, DIM, DIM, DIM, DIM, FFH};
    const int Cs[6] = {DIM, DIM, DIM, DIM, 2 * FFH, DIM};

    int tile = blockIdx.x, job = 0;
    #pragma unroll
    for (int j2 = 0; j2 < 6; j2++) {
        int nt = DEPTH * (Rs[j2] / 32) * (Cs[j2] / 32);
        if (tile >= nt) { tile -= nt; job++; }
        else break;
    }
    const int R = Rs[job], C = Cs[job];
    const int tpz = (R / 32) * (C / 32);
    const int zdx = tile / tpz;
    const int rem = tile - zdx * tpz;
    const int ty = rem / (C / 32), tx = rem - ty * (C / 32);
    const float* in = ins[job] + (long long)zdx * R * C;
    float* out = outs[job] + (long long)zdx * R * C;

    int c0 = tx * 32, r0 = ty * 32;
    int x = threadIdx.x & 31, y = threadIdx.x >> 5;
    #pragma unroll
    for (int i = 0; i < 32; i += 8)
        tbuf[y + i][x] = in[(long long)(r0 + y + i) * C + c0 + x];
    __syncthreads();
    #pragma unroll
    for (int i = 0; i < 32; i += 8)
        out[(long long)(c0 + y + i) * R + r0 + x] = tf32r(tbuf[x][y + i]);
}

// ---------------- cos/sin tables for rotary ----------------
__global__ void prep_trig(const float* __restrict__ srcf, const float* __restrict__ tgtf,
                          float* __restrict__ cS, float* __restrict__ sS,
                          float* __restrict__ cT, float* __restrict__ sT)
{
    int idx = blockIdx.x * blockDim.x + threadIdx.x;
    if (idx < NQ * DH) {
        float f = srcf[idx];
        cS[idx] = cosf(f); sS[idx] = sinf(f);
    } else if (idx < NQ * DH + MS * DH) {
        int i = idx - NQ * DH;
        float f = tgtf[i];
        cT[i] = cosf(f); sT[i] = sinf(f);
    }
}

// ---------------- V transpose per batch ----------------
__global__ void transpose_cvt(const float* __restrict__ in, float* __restrict__ out,
                              int R, int C, long long sIn, long long sOut)
{
    __shared__ float tbuf[32][33];
    in  += (long long)blockIdx.z * sIn;
    out += (long long)blockIdx.z * sOut;
    int c0 = blockIdx.x * 32, r0 = blockIdx.y * 32;
    int x = threadIdx.x, y = threadIdx.y;
    #pragma unroll
    for (int i = 0; i < 32; i += 8)
        tbuf[y + i][x] = in[(long long)(r0 + y + i) * C + c0 + x];
    __syncthreads();
    #pragma unroll
    for (int i = 0; i < 32; i += 8)
        out[(long long)(c0 + y + i) * R + r0 + x] = tf32r(tbuf[x][y + i]);
}

// ---------------- launcher ----------------
extern "C" void kernel_launch(void* const* d_in, const int* in_sizes, int n_in,
                              void* d_out, int out_size)
{
    const float* x    = (const float*)d_in[0];
    const float* cond = (const float*)d_in[1];
    const float* Wq   = (const float*)d_in[2];
    const float* Wk   = (const float*)d_in[3];
    const float* Wv   = (const float*)d_in[4];
    const float* Wo   = (const float*)d_in[5];
    const float* bo   = (const float*)d_in[6];
    const float* rpe  = (const float*)d_in[7];
    const float* W1   = (const float*)d_in[8];
    const float* b1   = (const float*)d_in[9];
    const float* W2   = (const float*)d_in[10];
    const float* b2   = (const float*)d_in[11];
    const float* srcf = (const float*)d_in[12];
    const float* tgtf = (const float*)d_in[13];
    const int*   reli = (const int*)d_in[14];
    float* xo = (float*)d_out;

    float *Q, *K, *V, *VT, *O, *Y;
    float *WqT, *WkT, *WvT, *WoT, *W1T, *W2T;
    float *cS, *sS, *cT, *sT;
    cudaGetSymbolAddress((void**)&Q, g_Q);
    cudaGetSymbolAddress((void**)&K, g_K);
    cudaGetSymbolAddress((void**)&V, g_V);
    cudaGetSymbolAddress((void**)&VT, g_VT);
    cudaGetSymbolAddress((void**)&O, g_O);
    cudaGetSymbolAddress((void**)&Y, g_Y);
    cudaGetSymbolAddress((void**)&WqT, g_WqT);
    cudaGetSymbolAddress((void**)&WkT, g_WkT);
    cudaGetSymbolAddress((void**)&WvT, g_WvT);
    cudaGetSymbolAddress((void**)&WoT, g_WoT);
    cudaGetSymbolAddress((void**)&W1T, g_W1T);
    cudaGetSymbolAddress((void**)&W2T, g_W2T);
    cudaGetSymbolAddress((void**)&cS, g_cosS);
    cudaGetSymbolAddress((void**)&sS, g_sinS);
    cudaGetSymbolAddress((void**)&cT, g_cosT);
    cudaGetSymbolAddress((void**)&sT, g_sinT);

    const int SM128 = (128 * 32 + 128 * 32) * 3 * 4;     // 96 KB
    const int SM64  = (128 * 32 + 64 * 32) * 3 * 4;      // 72 KB
    const int SMF1  = (128 * 32 + 2 * 64 * 32) * 3 * 4;  // 96 KB
    const int SMFL  = 32768 * 4;                         // 128 KB
    cudaFuncSetAttribute(gemm_tc<128, 0>, cudaFuncAttributeMaxDynamicSharedMemorySize, SM128);
    cudaFuncSetAttribute(gemm_tc<128, 2>, cudaFuncAttributeMaxDynamicSharedMemorySize, SM128);
    cudaFuncSetAttribute(gemm_tc<64, 0>,  cudaFuncAttributeMaxDynamicSharedMemorySize, SM64);
    cudaFuncSetAttribute(gemm_tc<64, 1>,  cudaFuncAttributeMaxDynamicSharedMemorySize, SM64);
    cudaFuncSetAttribute(gemm_ffn1, cudaFuncAttributeMaxDynamicSharedMemorySize, SMF1);
    cudaFuncSetAttribute(flash_attn, cudaFuncAttributeMaxDynamicSharedMemorySize, SMFL);

    cudaMemcpyAsync(xo, x, (size_t)MROWS * DIM * sizeof(float),
                    cudaMemcpyDeviceToDevice, 0);

    // launch 0: all weight transposes
    wtrans_all<<<32768, 256>>>(Wq, Wk, Wv, Wo, W1, W2, WqT, WkT, WvT, WoT, W1T, W2T);
    // launch 1: trig tables
    prep_trig<<<((NQ + MS) * DH + 255) / 256, 256>>>(srcf, tgtf, cS, sS, cT, sT);

    dim3 tb(32, 8);
    for (int l = 0; l < DEPTH; l++) {
        const float* wqt = WqT + (long long)l * DIM * DIM;
        const float* wkt = WkT + (long long)l * DIM * DIM;
        const float* wvt = WvT + (long long)l * DIM * DIM;
        const float* wot = WoT + (long long)l * DIM * DIM;
        const float* bol = bo + l * DIM;
        const float* rpel = rpe + (long long)l * 405 * HEADS;
        const float* w1t = W1T + (long long)l * DIM * 2 * FFH;
        const float* b1l = b1 + (long long)l * (2 * FFH);
        const float* w2t = W2T + (long long)l * DIM * FFH;
        const float* b2l = b2 + l * DIM;

        // Q = rope(x @ Wq) * SCALE      [launch 2 (+8/layer)]
        gemm_tc<64, 1><<<dim3(DIM / 64, MROWS / 128), 256, SM64>>>(
            xo, wqt, Q, nullptr, nullptr,
            DIM, DIM, DIM, DIM, 1.0f, cS, sS, nullptr, nullptr);
        // V = cond @ Wv                 [launch 3]
        gemm_tc<128, 0><<<dim3(DIM / 128, CROWS / 128), 256, SM128>>>(
            cond, wvt, V, nullptr, nullptr,
            DIM, DIM, DIM, DIM, 1.0f, nullptr, nullptr, nullptr, nullptr);
        // V^T per batch                 [launch 4]
        transpose_cvt<<<dim3(DIM / 32, JTOT / 32, BATCH), tb>>>(
            V, VT, JTOT, DIM, (long long)JTOT * DIM, (long long)DIM * JTOT);
        // K = rope_bias(cond @ Wk)      [launch 5 -> profiled]
        gemm_tc<128, 2><<<dim3(DIM / 128, CROWS / 128), 256, SM128>>>(
            cond, wkt, K, nullptr, nullptr,
            DIM, DIM, DIM, DIM, 1.0f, cT, sT, rpel, reli);

        // fused attention -> O          [launch 6]
        flash_attn<<<dim3(NQ / 128, BATCH * HEADS), 256, SMFL>>>(Q, K, VT, O);

        // x = x + O @ Wo + bo           [launch 7]
        gemm_tc<64, 0><<<dim3(DIM / 64, MROWS / 128), 256, SM64>>>(
            O, wot, xo, xo, bol,
            DIM, DIM, DIM, DIM, 1.0f, nullptr, nullptr, nullptr, nullptr);

        // Y = GEGLU(x @ W1 + b1)        [launch 8]
        gemm_ffn1<<<dim3(FFH / 64, MROWS / 128), 256, SMF1>>>(xo, w1t, Y, b1l);

        // x = x + Y @ W2 + b2           [launch 9]
        gemm_tc<64, 0><<<dim3(DIM / 64, MROWS / 128), 256, SM64>>>(
            Y, w2t, xo, xo, b2l,
            FFH, FFH, FFH, DIM, 1.0f, nullptr, nullptr, nullptr, nullptr);
    }
}

// round 6
// speedup vs baseline: 1.0648x; 1.0648x over previous
#include <cuda_runtime.h>
#include <math.h>
#include <stdint.h>

// ---------------- problem constants ----------------
#define DEPTH 2
#define DIM   1024
#define HEADS 16
#define DH    64
#define BATCH 8
#define NQ    256
#define JTOT  1088
#define MS    1024
#define MROWS (BATCH*NQ)    // 2048
#define CROWS (BATCH*JTOT)  // 8704
#define FFH   4096
#define SCALE 0.125f
#define NJT   17            // JTOT / 64

// ---------------- scratch ----------------
__device__ float g_Q[MROWS * DIM];
__device__ float g_K[CROWS * DIM];
__device__ float g_V[CROWS * DIM];
__device__ float g_VT[(long)BATCH * DIM * JTOT];
__device__ float g_O[MROWS * DIM];
__device__ float g_Y[(long)MROWS * FFH];
__device__ float g_WqT[(long)DEPTH * DIM * DIM];
__device__ float g_WkT[(long)DEPTH * DIM * DIM];
__device__ float g_WvT[(long)DEPTH * DIM * DIM];
__device__ float g_WoT[(long)DEPTH * DIM * DIM];
__device__ float g_W1T[(long)DEPTH * 2 * FFH * DIM];
__device__ float g_W2T[(long)DEPTH * DIM * FFH];
__device__ float g_cosS[NQ * DH];
__device__ float g_sinS[NQ * DH];
__device__ float g_cosT[MS * DH];
__device__ float g_sinT[MS * DH];

// ---------------- ptx helpers ----------------
__device__ __forceinline__ float tf32r(float f) {
    uint32_t u;
    asm("cvt.rna.tf32.f32 %0, %1;" : "=r"(u) : "f"(f));
    return __uint_as_float(u);
}
__device__ __forceinline__ void ldsm4(uint32_t* r, uint32_t a) {
    asm volatile("ldmatrix.sync.aligned.m8n8.x4.shared.b16 {%0,%1,%2,%3}, [%4];"
                 : "=r"(r[0]), "=r"(r[1]), "=r"(r[2]), "=r"(r[3]) : "r"(a));
}
__device__ __forceinline__ void ldsm2(uint32_t* r, uint32_t a) {
    asm volatile("ldmatrix.sync.aligned.m8n8.x2.shared.b16 {%0,%1}, [%2];"
                 : "=r"(r[0]), "=r"(r[1]) : "r"(a));
}
__device__ __forceinline__ void mma_tf32(float* c, const uint32_t* a, const uint32_t* b) {
    asm volatile(
        "mma.sync.aligned.m16n8k8.row.col.f32.tf32.tf32.f32 "
        "{%0,%1,%2,%3}, {%4,%5,%6,%7}, {%8,%9}, {%0,%1,%2,%3};"
        : "+f"(c[0]), "+f"(c[1]), "+f"(c[2]), "+f"(c[3])
        : "r"(a[0]), "r"(a[1]), "r"(a[2]), "r"(a[3]), "r"(b[0]), "r"(b[1]));
}
__device__ __forceinline__ void mma_tf32b(float* c, const uint32_t* a, uint32_t b0, uint32_t b1) {
    asm volatile(
        "mma.sync.aligned.m16n8k8.row.col.f32.tf32.tf32.f32 "
        "{%0,%1,%2,%3}, {%4,%5,%6,%7}, {%8,%9}, {%0,%1,%2,%3};"
        : "+f"(c[0]), "+f"(c[1]), "+f"(c[2]), "+f"(c[3])
        : "r"(a[0]), "r"(a[1]), "r"(a[2]), "r"(a[3]), "r"(b0), "r"(b1));
}
__device__ __forceinline__ void cpa16(uint32_t d, const float* s) {
    asm volatile("cp.async.cg.shared.global [%0], [%1], 16;" :: "r"(d), "l"(s));
}

// ---------------- tf32 GEMM; EPI: 0=plain, 1=rope_q+scale, 2=rpe_bias+rope_k --
template <int BN, int EPI>
__global__ void __launch_bounds__(256, 2)
gemm_tc(const float* __restrict__ A, const float* __restrict__ B,
        float* __restrict__ C, const float* __restrict__ Cadd,
        const float* __restrict__ bias,
        int K, int lda, int ldb, int ldc, float alpha,
        const float* __restrict__ ctab, const float* __restrict__ stab,
        const float* __restrict__ rpe_l, const int* __restrict__ rel_idx)
{
    constexpr int BM = 128;
    constexpr int ASZ = BM * 32, BSZ = BN * 32, STF = ASZ + BSZ;
    constexpr int WN = (BN == 128) ? 4 : 2;
    constexpr int WTM = BM / (8 / WN), WTN = BN / WN;
    constexpr int MI = WTM / 16, NI = WTN / 8;

    extern __shared__ float smdyn[];
    const uint32_t sb = (uint32_t)__cvta_generic_to_shared(smdyn);

    const int tid = threadIdx.x, warp = tid >> 5, lane = tid & 31;
    const int wm = warp / WN, wn = warp % WN;
    const int g = lane >> 2, t = lane & 3;
    const int bm0 = blockIdx.y * BM, bn0 = blockIdx.x * BN;

    const int arow = tid >> 3;
    const int cc   = tid & 7;

    const float* Ag = A + (long long)(bm0 + arow) * lda + cc * 4;
    const float* Bg = B + (long long)(bn0 + arow) * ldb + cc * 4;

    const int KT = K >> 5;

    auto load_stage = [&](int s, int kt) {
        if (kt < KT) {
            const int k0 = kt << 5;
            uint32_t ab = sb + (uint32_t)(s * STF) * 4u;
            #pragma unroll
            for (int i = 0; i < 4; i++) {
                int r = arow + i * 32;
                cpa16(ab + r * 128 + ((cc ^ (r & 7)) << 4),
                      Ag + (long long)i * 32 * lda + k0);
            }
            uint32_t bb = sb + (uint32_t)(s * STF + ASZ) * 4u;
            #pragma unroll
            for (int i = 0; i < BN / 32; i++) {
                int r = arow + i * 32;
                cpa16(bb + r * 128 + ((cc ^ (r & 7)) << 4),
                      Bg + (long long)i * 32 * ldb + k0);
            }
        }
        asm volatile("cp.async.commit_group;");
    };

    float acc[MI][NI][4];
    #pragma unroll
    for (int mi = 0; mi < MI; mi++)
        #pragma unroll
        for (int ni = 0; ni < NI; ni++)
            #pragma unroll
            for (int q = 0; q < 4; q++) acc[mi][ni][q] = 0.f;

    const int a_r  = lane & 15;
    const int a_kc = lane >> 4;
    const int b_r  = lane & 7;
    const int b_kc = (lane >> 3) & 1;

    load_stage(0, 0);
    load_stage(1, 1);

    for (int kt = 0; kt < KT; kt++) {
        asm volatile("cp.async.wait_group 1;");
        __syncthreads();
        load_stage((kt + 2) % 3, kt + 2);

        const int s = kt % 3;
        const uint32_t ab = sb + (uint32_t)(s * STF) * 4u;
        const uint32_t bb = ab + (uint32_t)ASZ * 4u;

        #pragma unroll
        for (int kk = 0; kk < 4; kk++) {
            uint32_t af[MI][4], bf[NI][2];
            #pragma unroll
            for (int mi = 0; mi < MI; mi++) {
                int r = wm * WTM + mi * 16 + a_r;
                int kc = kk * 2 + a_kc;
                ldsm4(af[mi], ab + r * 128 + ((kc ^ (r & 7)) << 4));
            }
            #pragma unroll
            for (int ni = 0; ni < NI; ni++) {
                int r = wn * WTN + ni * 8 + b_r;
                int kc = kk * 2 + b_kc;
                ldsm2(bf[ni], bb + r * 128 + ((kc ^ (r & 7)) << 4));
            }
            #pragma unroll
            for (int mi = 0; mi < MI; mi++)
                #pragma unroll
                for (int ni = 0; ni < NI; ni++)
                    mma_tf32(acc[mi][ni], af[mi], bf[ni]);
        }
    }

    #pragma unroll
    for (int mi = 0; mi < MI; mi++) {
        int row0 = bm0 + wm * WTM + mi * 16 + g;
        int jA = 0, jB = 0;
        if (EPI == 2) { jA = row0 % JTOT; jB = (row0 + 8) % JTOT; }
        #pragma unroll
        for (int ni = 0; ni < NI; ni++) {
            int col = bn0 + wn * WTN + ni * 8 + 2 * t;
            float v0 = alpha * acc[mi][ni][0];
            float v1 = alpha * acc[mi][ni][1];
            float v2 = alpha * acc[mi][ni][2];
            float v3 = alpha * acc[mi][ni][3];
            if (bias) { float b0 = bias[col], b1 = bias[col + 1]; v0 += b0; v1 += b1; v2 += b0; v3 += b1; }
            if (Cadd) {
                const float2 c0 = *(const float2*)(Cadd + (long long)row0 * ldc + col);
                const float2 c1 = *(const float2*)(Cadd + (long long)(row0 + 8) * ldc + col);
                v0 += c0.x; v1 += c0.y; v2 += c1.x; v3 += c1.y;
            }
            if (EPI == 1) {
                int d = col & (DH - 1);
                int nA = row0 & (NQ - 1), nB = (row0 + 8) & (NQ - 1);
                float cA0 = ctab[nA * DH + d],     sA0 = stab[nA * DH + d];
                float cA1 = ctab[nA * DH + d + 1], sA1 = stab[nA * DH + d + 1];
                float cB0 = ctab[nB * DH + d],     sB0 = stab[nB * DH + d];
                float cB1 = ctab[nB * DH + d + 1], sB1 = stab[nB * DH + d + 1];
                float o0 = (v0 * cA0 - v1 * sA0) * SCALE;
                float o1 = (v1 * cA1 + v0 * sA1) * SCALE;
                float o2 = (v2 * cB0 - v3 * sB0) * SCALE;
                float o3 = (v3 * cB1 + v2 * sB1) * SCALE;
                v0 = o0; v1 = o1; v2 = o2; v3 = o3;
            }
            if (EPI == 2) {
                int d = col & (DH - 1);
                int h = col >> 6;
                if (jA < MS) {
                    float bb2 = rpe_l[rel_idx[jA >> 8] * HEADS + h];
                    float k0 = v0 + bb2, k1 = v1 + bb2;
                    float c0 = ctab[jA * DH + d],     s0 = stab[jA * DH + d];
                    float c1 = ctab[jA * DH + d + 1], s1 = stab[jA * DH + d + 1];
                    v0 = k0 * c0 - k1 * s0;
                    v1 = k1 * c1 + k0 * s1;
                }
                if (jB < MS) {
                    float bb2 = rpe_l[rel_idx[jB >> 8] * HEADS + h];
                    float k0 = v2 + bb2, k1 = v3 + bb2;
                    float c0 = ctab[jB * DH + d],     s0 = stab[jB * DH + d];
                    float c1 = ctab[jB * DH + d + 1], s1 = stab[jB * DH + d + 1];
                    v2 = k0 * c0 - k1 * s0;
                    v3 = k1 * c1 + k0 * s1;
                }
            }
            *(float2*)(C + (long long)row0 * ldc + col) = make_float2(v0, v1);
            *(float2*)(C + (long long)(row0 + 8) * ldc + col) = make_float2(v2, v3);
        }
    }
}

// ---------------- FFN1 + GEGLU fused ----------------
__global__ void __launch_bounds__(256, 2)
gemm_ffn1(const float* __restrict__ A, const float* __restrict__ B,
          float* __restrict__ Y, const float* __restrict__ b1l)
{
    constexpr int BM = 128, BN = 64;
    constexpr int ASZ = BM * 32, BSZ = BN * 32, STF = ASZ + 2 * BSZ;
    constexpr int WTM = 32, WTN = 32, MI = 2, NI = 4;
    const int KT = 32;

    extern __shared__ float smdyn[];
    const uint32_t sb = (uint32_t)__cvta_generic_to_shared(smdyn);

    const int tid = threadIdx.x, warp = tid >> 5, lane = tid & 31;
    const int wm = warp >> 1, wn = warp & 1;
    const int g = lane >> 2, t = lane & 3;
    const int bm0 = blockIdx.y * BM, bn0 = blockIdx.x * BN;

    const int arow = tid >> 3;
    const int cc   = tid & 7;

    const float* Ag  = A + (long long)(bm0 + arow) * DIM + cc * 4;
    const float* Bga = B + (long long)(bn0 + arow) * DIM + cc * 4;
    const float* Bgg = B + (long long)(FFH + bn0 + arow) * DIM + cc * 4;

    auto load_stage = [&](int s, int kt) {
        if (kt < KT) {
            const int k0 = kt << 5;
            uint32_t ab = sb + (uint32_t)(s * STF) * 4u;
            #pragma unroll
            for (int i = 0; i < 4; i++) {
                int r = arow + i * 32;
                cpa16(ab + r * 128 + ((cc ^ (r & 7)) << 4),
                      Ag + (long long)i * 32 * DIM + k0);
            }
            uint32_t bba = sb + (uint32_t)(s * STF + ASZ) * 4u;
            uint32_t bbg = bba + (uint32_t)BSZ * 4u;
            #pragma unroll
            for (int i = 0; i < 2; i++) {
                int r = arow + i * 32;
                cpa16(bba + r * 128 + ((cc ^ (r & 7)) << 4),
                      Bga + (long long)i * 32 * DIM + k0);
                cpa16(bbg + r * 128 + ((cc ^ (r & 7)) << 4),
                      Bgg + (long long)i * 32 * DIM + k0);
            }
        }
        asm volatile("cp.async.commit_group;");
    };

    float acca[MI][NI][4], accg[MI][NI][4];
    #pragma unroll
    for (int mi = 0; mi < MI; mi++)
        #pragma unroll
        for (int ni = 0; ni < NI; ni++)
            #pragma unroll
            for (int q = 0; q < 4; q++) { acca[mi][ni][q] = 0.f; accg[mi][ni][q] = 0.f; }

    const int a_r  = lane & 15;
    const int a_kc = lane >> 4;
    const int b_r  = lane & 7;
    const int b_kc = (lane >> 3) & 1;

    load_stage(0, 0);
    load_stage(1, 1);

    for (int kt = 0; kt < KT; kt++) {
        asm volatile("cp.async.wait_group 1;");
        __syncthreads();
        load_stage((kt + 2) % 3, kt + 2);

        const int s = kt % 3;
        const uint32_t ab  = sb + (uint32_t)(s * STF) * 4u;
        const uint32_t bba = ab + (uint32_t)ASZ * 4u;
        const uint32_t bbg = bba + (uint32_t)BSZ * 4u;

        #pragma unroll
        for (int kk = 0; kk < 4; kk++) {
            uint32_t af[MI][4], bfa[NI][2], bfg[NI][2];
            #pragma unroll
            for (int mi = 0; mi < MI; mi++) {
                int r = wm * WTM + mi * 16 + a_r;
                int kc = kk * 2 + a_kc;
                ldsm4(af[mi], ab + r * 128 + ((kc ^ (r & 7)) << 4));
            }
            #pragma unroll
            for (int ni = 0; ni < NI; ni++) {
                int r = wn * WTN + ni * 8 + b_r;
                int kc = kk * 2 + b_kc;
                ldsm2(bfa[ni], bba + r * 128 + ((kc ^ (r & 7)) << 4));
                ldsm2(bfg[ni], bbg + r * 128 + ((kc ^ (r & 7)) << 4));
            }
            #pragma unroll
            for (int mi = 0; mi < MI; mi++)
                #pragma unroll
                for (int ni = 0; ni < NI; ni++) {
                    mma_tf32(acca[mi][ni], af[mi], bfa[ni]);
                    mma_tf32(accg[mi][ni], af[mi], bfg[ni]);
                }
        }
    }

    #pragma unroll
    for (int mi = 0; mi < MI; mi++) {
        int row0 = bm0 + wm * WTM + mi * 16 + g;
        #pragma unroll
        for (int ni = 0; ni < NI; ni++) {
            int col = bn0 + wn * WTN + ni * 8 + 2 * t;
            float ba0 = b1l[col], ba1 = b1l[col + 1];
            float bg0 = b1l[FFH + col], bg1 = b1l[FFH + col + 1];
            #pragma unroll
            for (int half = 0; half < 2; half++) {
                float a0 = acca[mi][ni][half * 2 + 0] + ba0;
                float a1 = acca[mi][ni][half * 2 + 1] + ba1;
                float g0 = accg[mi][ni][half * 2 + 0] + bg0;
                float g1 = accg[mi][ni][half * 2 + 1] + bg1;
                float y0 = a0 * (0.5f * g0 * (1.0f + erff(g0 * 0.70710678118654752f)));
                float y1 = a1 * (0.5f * g1 * (1.0f + erff(g1 * 0.70710678118654752f)));
                *(float2*)(Y + (long long)(row0 + half * 8) * FFH + col) = make_float2(y0, y1);
            }
        }
    }
}

// ---------------- flash attention ----------------
__global__ void __launch_bounds__(256)
flash_attn(const float* __restrict__ Q, const float* __restrict__ K,
           const float* __restrict__ VT, float* __restrict__ O)
{
    extern __shared__ float sm[];
    const uint32_t sb = (uint32_t)__cvta_generic_to_shared(sm);
    const uint32_t qb = sb;
    const uint32_t kb = sb + 8192u * 4u;
    const uint32_t vb = sb + 16384u * 4u;
    const uint32_t pb = sb + 24576u * 4u;

    const int tid = threadIdx.x, warp = tid >> 5, lane = tid & 31;
    const int g = lane >> 2, t = lane & 3;
    const int m0 = blockIdx.x * 128;
    const int z = blockIdx.y;
    const int b = z >> 4, h = z & 15;

    const float* Qg = Q + ((long long)(b * NQ + m0)) * DIM + h * DH;
    const float* Kg = K + (long long)b * JTOT * DIM + h * DH;
    const float* Vg = VT + (long long)b * DIM * JTOT + (long long)h * DH * JTOT;
    float* Og = O + ((long long)(b * NQ + m0)) * DIM + h * DH;

    auto load_kv_body = [&](int s, int jt) {
        #pragma unroll
        for (int i = 0; i < 4; i++) {
            int idx = tid + i * 256;
            int cc = idx & 7, r = (idx >> 3) & 63, hf = idx >> 9;
            uint32_t off = (uint32_t)(s * 4096 + (hf * 64 + r) * 32) * 4u + ((cc ^ (r & 7)) << 4);
            cpa16(kb + off, Kg + (long long)(jt * 64 + r) * DIM + hf * 32 + cc * 4);
            cpa16(vb + off, Vg + (long long)r * JTOT + jt * 64 + hf * 32 + cc * 4);
        }
    };

    #pragma unroll
    for (int i = 0; i < 8; i++) {
        int idx = tid + i * 256;
        int cc = idx & 7, r = (idx >> 3) & 127, hf = idx >> 10;
        cpa16(qb + (uint32_t)(hf * 128 + r) * 128u + ((cc ^ (r & 7)) << 4),
              Qg + (long long)r * DIM + hf * 32 + cc * 4);
    }
    load_kv_body(0, 0);
    asm volatile("cp.async.commit_group;");
    load_kv_body(1, 1);
    asm volatile("cp.async.commit_group;");

    float acco[8][4];
    #pragma unroll
    for (int ni = 0; ni < 8; ni++)
        #pragma unroll
        for (int q = 0; q < 4; q++) acco[ni][q] = 0.f;
    float mr0 = -INFINITY, mr1 = -INFINITY, l0 = 0.f, l1 = 0.f;

    const int fr = lane & 15;
    const int fc = lane >> 4;

    for (int jt = 0; jt < NJT; jt++) {
        const int s = jt & 1;
        asm volatile("cp.async.wait_group 1;");
        __syncthreads();

        float accs[8][4];
        #pragma unroll
        for (int ni = 0; ni < 8; ni++)
            #pragma unroll
            for (int q = 0; q < 4; q++) accs[ni][q] = 0.f;

        #pragma unroll
        for (int kk = 0; kk < 8; kk++) {
            const int hf = kk >> 2;
            const int kc = (kk & 3) * 2 + fc;
            uint32_t a[4];
            {
                int r = warp * 16 + fr;
                ldsm4(a, qb + (uint32_t)(hf * 128 + r) * 128u + ((kc ^ (r & 7)) << 4));
            }
            #pragma unroll
            for (int p = 0; p < 4; p++) {
                int r = p * 16 + fr;
                uint32_t bf[4];
                ldsm4(bf, kb + (uint32_t)(s * 4096 + (hf * 64 + r) * 32) * 4u + ((kc ^ (r & 7)) << 4));
                mma_tf32b(accs[2 * p],     a, bf[0], bf[2]);
                mma_tf32b(accs[2 * p + 1], a, bf[1], bf[3]);
            }
        }

        float vm0 = -INFINITY, vm1 = -INFINITY;
        #pragma unroll
        for (int ni = 0; ni < 8; ni++) {
            vm0 = fmaxf(vm0, fmaxf(accs[ni][0], accs[ni][1]));
            vm1 = fmaxf(vm1, fmaxf(accs[ni][2], accs[ni][3]));
        }
        vm0 = fmaxf(vm0, __shfl_xor_sync(0xffffffffu, vm0, 1));
        vm0 = fmaxf(vm0, __shfl_xor_sync(0xffffffffu, vm0, 2));
        vm1 = fmaxf(vm1, __shfl_xor_sync(0xffffffffu, vm1, 1));
        vm1 = fmaxf(vm1, __shfl_xor_sync(0xffffffffu, vm1, 2));
        float mn0 = fmaxf(mr0, vm0), mn1 = fmaxf(mr1, vm1);
        float sc0 = __expf(mr0 - mn0), sc1 = __expf(mr1 - mn1);

        float ps0 = 0.f, ps1 = 0.f;
        float pv[8][4];
        #pragma unroll
        for (int ni = 0; ni < 8; ni++) {
            pv[ni][0] = tf32r(__expf(accs[ni][0] - mn0));
            pv[ni][1] = tf32r(__expf(accs[ni][1] - mn0));
            pv[ni][2] = tf32r(__expf(accs[ni][2] - mn1));
            pv[ni][3] = tf32r(__expf(accs[ni][3] - mn1));
            ps0 += pv[ni][0] + pv[ni][1];
            ps1 += pv[ni][2] + pv[ni][3];
        }
        ps0 += __shfl_xor_sync(0xffffffffu, ps0, 1);
        ps0 += __shfl_xor_sync(0xffffffffu, ps0, 2);
        ps1 += __shfl_xor_sync(0xffffffffu, ps1, 1);
        ps1 += __shfl_xor_sync(0xffffffffu, ps1, 2);
        l0 = l0 * sc0 + ps0;
        l1 = l1 * sc1 + ps1;
        mr0 = mn0; mr1 = mn1;
        #pragma unroll
        for (int ni = 0; ni < 8; ni++) {
            acco[ni][0] *= sc0; acco[ni][1] *= sc0;
            acco[ni][2] *= sc1; acco[ni][3] *= sc1;
        }

        const int r0 = warp * 16 + g, r1 = r0 + 8;
        #pragma unroll
        for (int ni = 0; ni < 8; ni++) {
            int hf = ni >> 2;
            int cc = (ni & 3) * 2 + (t >> 1);
            uint32_t ofs = (uint32_t)((t & 1) * 8);
            uint32_t a0 = pb + (uint32_t)(hf * 128 + r0) * 128u + ((cc ^ (r0 & 7)) << 4) + ofs;
            uint32_t a1 = pb + (uint32_t)(hf * 128 + r1) * 128u + ((cc ^ (r1 & 7)) << 4) + ofs;
            asm volatile("st.shared.v2.f32 [%0], {%1,%2};" :: "r"(a0), "f"(pv[ni][0]), "f"(pv[ni][1]));
            asm volatile("st.shared.v2.f32 [%0], {%1,%2};" :: "r"(a1), "f"(pv[ni][2]), "f"(pv[ni][3]));
        }
        __syncwarp();

        #pragma unroll
        for (int kk = 0; kk < 8; kk++) {
            const int hf = kk >> 2;
            const int kc = (kk & 3) * 2 + fc;
            uint32_t a[4];
            {
                int r = warp * 16 + fr;
                ldsm4(a, pb + (uint32_t)(hf * 128 + r) * 128u + ((kc ^ (r & 7)) << 4));
            }
            #pragma unroll
            for (int p = 0; p < 4; p++) {
                int r = p * 16 + fr;
                uint32_t bf[4];
                ldsm4(bf, vb + (uint32_t)(s * 4096 + (hf * 64 + r) * 32) * 4u + ((kc ^ (r & 7)) << 4));
                mma_tf32b(acco[2 * p],     a, bf[0], bf[2]);
                mma_tf32b(acco[2 * p + 1], a, bf[1], bf[3]);
            }
        }
        __syncthreads();

        if (jt + 2 < NJT) load_kv_body(s, jt + 2);
        asm volatile("cp.async.commit_group;");
    }

    float inv0 = 1.f / l0, inv1 = 1.f / l1;
    const int r0 = warp * 16 + g, r1 = r0 + 8;
    #pragma unroll
    for (int ni = 0; ni < 8; ni++) {
        int col = ni * 8 + 2 * t;
        *(float2*)(Og + (long long)r0 * DIM + col) =
            make_float2(acco[ni][0] * inv0, acco[ni][1] * inv0);
        *(float2*)(Og + (long long)r1 * DIM + col) =
            make_float2(acco[ni][2] * inv1, acco[ni][3] * inv1);
    }
}

// ---------------- batched weight transpose (single launch) ----------------
__global__ void __launch_bounds__(256)
wtrans_all(const float* __restrict__ Wq, const float* __restrict__ Wk,
           const float* __restrict__ Wv, const float* __restrict__ Wo,
           const float* __restrict__ W1, const float* __restrict__ W2,
           float* __restrict__ WqT, float* __restrict__ WkT,
           float* __restrict__ WvT, float* __restrict__ WoT,
           float* __restrict__ W1T, float* __restrict__ W2T)
{
    __shared__ float tbuf[32][33];
    const float* ins[6] = {Wq, Wk, Wv, Wo, W1, W2};
    float* outs[6] = {WqT, WkT, WvT, WoT, W1T, W2T};
    const int Rs[6] = {DIM, DIM, DIM, DIM, DIM, FFH};
    const int Cs[6] = {DIM, DIM, DIM, DIM, 2 * FFH, DIM};

    int tile = blockIdx.x, job = 0;
    #pragma unroll
    for (int j2 = 0; j2 < 6; j2++) {
        int nt = DEPTH * (Rs[j2] / 32) * (Cs[j2] / 32);
        if (tile >= nt) { tile -= nt; job++; }
        else break;
    }
    const int R = Rs[job], C = Cs[job];
    const int tpz = (R / 32) * (C / 32);
    const int zdx = tile / tpz;
    const int rem = tile - zdx * tpz;
    const int ty = rem / (C / 32), tx = rem - ty * (C / 32);
    const float* in = ins[job] + (long long)zdx * R * C;
    float* out = outs[job] + (long long)zdx * R * C;

    int c0 = tx * 32, r0 = ty * 32;
    int x = threadIdx.x & 31, y = threadIdx.x >> 5;
    #pragma unroll
    for (int i = 0; i < 32; i += 8)
        tbuf[y + i][x] = in[(long long)(r0 + y + i) * C + c0 + x];
    __syncthreads();
    #pragma unroll
    for (int i = 0; i < 32; i += 8)
        out[(long long)(c0 + y + i) * R + r0 + x] = tf32r(tbuf[x][y + i]);
}

// ---------------- cos/sin tables for rotary ----------------
__global__ void prep_trig(const float* __restrict__ srcf, const float* __restrict__ tgtf,
                          float* __restrict__ cS, float* __restrict__ sS,
                          float* __restrict__ cT, float* __restrict__ sT)
{
    int idx = blockIdx.x * blockDim.x + threadIdx.x;
    if (idx < NQ * DH) {
        float f = srcf[idx];
        cS[idx] = cosf(f); sS[idx] = sinf(f);
    } else if (idx < NQ * DH + MS * DH) {
        int i = idx - NQ * DH;
        float f = tgtf[i];
        cT[i] = cosf(f); sT[i] = sinf(f);
    }
}

// ---------------- V transpose per batch ----------------
__global__ void transpose_cvt(const float* __restrict__ in, float* __restrict__ out,
                              int R, int C, long long sIn, long long sOut)
{
    __shared__ float tbuf[32][33];
    in  += (long long)blockIdx.z * sIn;
    out += (long long)blockIdx.z * sOut;
    int c0 = blockIdx.x * 32, r0 = blockIdx.y * 32;
    int x = threadIdx.x, y = threadIdx.y;
    #pragma unroll
    for (int i = 0; i < 32; i += 8)
        tbuf[y + i][x] = in[(long long)(r0 + y + i) * C + c0 + x];
    __syncthreads();
    #pragma unroll
    for (int i = 0; i < 32; i += 8)
        out[(long long)(c0 + y + i) * R + r0 + x] = tf32r(tbuf[x][y + i]);
}

// ---------------- launcher ----------------
extern "C" void kernel_launch(void* const* d_in, const int* in_sizes, int n_in,
                              void* d_out, int out_size)
{
    const float* x    = (const float*)d_in[0];
    const float* cond = (const float*)d_in[1];
    const float* Wq   = (const float*)d_in[2];
    const float* Wk   = (const float*)d_in[3];
    const float* Wv   = (const float*)d_in[4];
    const float* Wo   = (const float*)d_in[5];
    const float* bo   = (const float*)d_in[6];
    const float* rpe  = (const float*)d_in[7];
    const float* W1   = (const float*)d_in[8];
    const float* b1   = (const float*)d_in[9];
    const float* W2   = (const float*)d_in[10];
    const float* b2   = (const float*)d_in[11];
    const float* srcf = (const float*)d_in[12];
    const float* tgtf = (const float*)d_in[13];
    const int*   reli = (const int*)d_in[14];
    float* xo = (float*)d_out;

    float *Q, *K, *V, *VT, *O, *Y;
    float *WqT, *WkT, *WvT, *WoT, *W1T, *W2T;
    float *cS, *sS, *cT, *sT;
    cudaGetSymbolAddress((void**)&Q, g_Q);
    cudaGetSymbolAddress((void**)&K, g_K);
    cudaGetSymbolAddress((void**)&V, g_V);
    cudaGetSymbolAddress((void**)&VT, g_VT);
    cudaGetSymbolAddress((void**)&O, g_O);
    cudaGetSymbolAddress((void**)&Y, g_Y);
    cudaGetSymbolAddress((void**)&WqT, g_WqT);
    cudaGetSymbolAddress((void**)&WkT, g_WkT);
    cudaGetSymbolAddress((void**)&WvT, g_WvT);
    cudaGetSymbolAddress((void**)&WoT, g_WoT);
    cudaGetSymbolAddress((void**)&W1T, g_W1T);
    cudaGetSymbolAddress((void**)&W2T, g_W2T);
    cudaGetSymbolAddress((void**)&cS, g_cosS);
    cudaGetSymbolAddress((void**)&sS, g_sinS);
    cudaGetSymbolAddress((void**)&cT, g_cosT);
    cudaGetSymbolAddress((void**)&sT, g_sinT);

    const int SM128 = (128 * 32 + 128 * 32) * 3 * 4;     // 96 KB
    const int SMF1  = (128 * 32 + 2 * 64 * 32) * 3 * 4;  // 96 KB
    const int SMFL  = 32768 * 4;                         // 128 KB
    cudaFuncSetAttribute(gemm_tc<128, 0>, cudaFuncAttributeMaxDynamicSharedMemorySize, SM128);
    cudaFuncSetAttribute(gemm_tc<128, 1>, cudaFuncAttributeMaxDynamicSharedMemorySize, SM128);
    cudaFuncSetAttribute(gemm_tc<128, 2>, cudaFuncAttributeMaxDynamicSharedMemorySize, SM128);
    cudaFuncSetAttribute(gemm_ffn1, cudaFuncAttributeMaxDynamicSharedMemorySize, SMF1);
    cudaFuncSetAttribute(flash_attn, cudaFuncAttributeMaxDynamicSharedMemorySize, SMFL);

    cudaMemcpyAsync(xo, x, (size_t)MROWS * DIM * sizeof(float),
                    cudaMemcpyDeviceToDevice, 0);

    wtrans_all<<<32768, 256>>>(Wq, Wk, Wv, Wo, W1, W2, WqT, WkT, WvT, WoT, W1T, W2T);
    prep_trig<<<((NQ + MS) * DH + 255) / 256, 256>>>(srcf, tgtf, cS, sS, cT, sT);

    dim3 tb(32, 8);
    for (int l = 0; l < DEPTH; l++) {
        const float* wqt = WqT + (long long)l * DIM * DIM;
        const float* wkt = WkT + (long long)l * DIM * DIM;
        const float* wvt = WvT + (long long)l * DIM * DIM;
        const float* wot = WoT + (long long)l * DIM * DIM;
        const float* bol = bo + l * DIM;
        const float* rpel = rpe + (long long)l * 405 * HEADS;
        const float* w1t = W1T + (long long)l * DIM * 2 * FFH;
        const float* b1l = b1 + (long long)l * (2 * FFH);
        const float* w2t = W2T + (long long)l * DIM * FFH;
        const float* b2l = b2 + l * DIM;

        // Q = rope(x @ Wq) * SCALE
        gemm_tc<128, 1><<<dim3(DIM / 128, MROWS / 128), 256, SM128>>>(
            xo, wqt, Q, nullptr, nullptr,
            DIM, DIM, DIM, DIM, 1.0f, cS, sS, nullptr, nullptr);
        // V = cond @ Wv
        gemm_tc<128, 0><<<dim3(DIM / 128, CROWS / 128), 256, SM128>>>(
            cond, wvt, V, nullptr, nullptr,
            DIM, DIM, DIM, DIM, 1.0f, nullptr, nullptr, nullptr, nullptr);
        // V^T per batch
        transpose_cvt<<<dim3(DIM / 32, JTOT / 32, BATCH), tb>>>(
            V, VT, JTOT, DIM, (long long)JTOT * DIM, (long long)DIM * JTOT);
        // K = rope_bias(cond @ Wk)
        gemm_tc<128, 2><<<dim3(DIM / 128, CROWS / 128), 256, SM128>>>(
            cond, wkt, K, nullptr, nullptr,
            DIM, DIM, DIM, DIM, 1.0f, cT, sT, rpel, reli);

        // fused attention -> O
        flash_attn<<<dim3(NQ / 128, BATCH * HEADS), 256, SMFL>>>(Q, K, VT, O);

        // x = x + O @ Wo + bo
        gemm_tc<128, 0><<<dim3(DIM / 128, MROWS / 128), 256, SM128>>>(
            O, wot, xo, xo, bol,
            DIM, DIM, DIM, DIM, 1.0f, nullptr, nullptr, nullptr, nullptr);

        // Y = GEGLU(x @ W1 + b1)
        gemm_ffn1<<<dim3(FFH / 64, MROWS / 128), 256, SMF1>>>(xo, w1t, Y, b1l);

        // x = x + Y @ W2 + b2
        gemm_tc<128, 0><<<dim3(DIM / 128, MROWS / 128), 256, SM128>>>(
            Y, w2t, xo, xo, b2l,
            FFH, FFH, FFH, DIM, 1.0f, nullptr, nullptr, nullptr, nullptr);
    }
}